// round 12
// baseline (speedup 1.0000x reference)
#include <cuda_runtime.h>
#include <cstdint>

#define B 2
#define N 2048
#define C 768
#define CG 192                      // C/4 float4 groups
#define G 512                       // 4 CTAs/SM co-resident (592 capacity)
#define T 256
#define ROWS_PER 8                  // X rows per CTA
#define CHUNKS 256                  // per batch
#define NJ3 384                     // CTAs doing P3 (2 j-rows each)
#define XBUF_BYTES (ROWS_PER * C * 4)        // 24576
#define SH_OFF XBUF_BYTES
#define SMEM_BYTES (SH_OFF + 2 * CG * 16)    // 30720
#define NREL 64                     // release lines (8 pollers each)

__device__ float4 g_part[B][CHUNKS][CG];
__device__ float  g_s[B][C];
__device__ float4 g_vpart[B][NJ3][CG];
__device__ float  g_v[B][C];

struct __align__(128) Cnt { unsigned v; unsigned pad[31]; };
__device__ Cnt g_arr[4];            // arrival counters (monotonic)
__device__ Cnt g_rel[4][NREL];      // release epochs, each on own line

__device__ __forceinline__ float4 f4add(float4 a, float4 b) {
    return make_float4(a.x + b.x, a.y + b.y, a.z + b.z, a.w + b.w);
}
__device__ __forceinline__ float4 f4fma(float4 a, float s, float4 acc) {
    return make_float4(fmaf(a.x, s, acc.x), fmaf(a.y, s, acc.y),
                       fmaf(a.z, s, acc.z), fmaf(a.w, s, acc.w));
}

// Release helper: last arriver publishes epoch to all NREL lines.
__device__ __forceinline__ void bar_release(int i, unsigned old) {
    if (old % G == G - 1u) {
        unsigned e = old / G + 1u;
#pragma unroll
        for (int k = 0; k < NREL; ++k)
            *(volatile unsigned*)&g_rel[i][k].v = e;
    }
}

// Full barrier: arrive + wait. Baseline read of my release line BEFORE my
// arrival is race-free (line bumps only after all G arrive). Monotonic ->
// replay-safe without reset.
__device__ __forceinline__ void grid_barrier(int i, int ct) {
    __threadfence();
    __syncthreads();
    if (threadIdx.x == 0) {
        volatile unsigned* fp = &g_rel[i][ct & (NREL - 1)].v;
        unsigned base = *fp;
        unsigned old = atomicAdd(&g_arr[i].v, 1u);
        bar_release(i, old);
        while (*fp < base + 1u) { }
        __threadfence();
    }
    __syncthreads();
}
// Arrive-only (never waits) — must still handle being the last arriver.
__device__ __forceinline__ void grid_barrier_arrive(int i) {
    __threadfence();
    __syncthreads();
    if (threadIdx.x == 0) {
        unsigned old = atomicAdd(&g_arr[i].v, 1u);
        bar_release(i, old);
    }
}

extern __shared__ char smem_raw[];

__global__ void __launch_bounds__(T, 4)
fused_att_scores(const float4* __restrict__ X4, const float4* __restrict__ W4,
                 float* __restrict__ out) {
    float4* xbuf = (float4*)smem_raw;              // 24 KB: 8 X rows (retained)
    float4* sh   = (float4*)(smem_raw + SH_OFF);   // 6 KB staging
    __shared__ float u0s[2], u1s[2];
    const int ct  = blockIdx.x;
    const int tid = threadIdx.x;
    const int wid = tid >> 5, lane = tid & 31;
    const bool reducer = (ct < 32);
    const bool p3er = (ct < NJ3);

    const int b = ct & 1, chunk = ct >> 1;         // 256 chunks per batch
    const int j0 = ct * 2;                         // P3: 2 j-rows (ct < 384)

    // t=0: prefetch this CTA's W rows into L2 (P3 participants only).
    if (p3er && tid < 48) {
        const char* wqp = (const char*)(W4 + (size_t)j0 * CG);
        const char* wkp = (const char*)(W4 + (size_t)(C + j0) * CG);
        asm volatile("prefetch.global.L2 [%0];" :: "l"(wqp + tid * 128));
        asm volatile("prefetch.global.L2 [%0];" :: "l"(wkp + tid * 128));
    }

    // ---- P1: warp w loads X row w (6 independent LDG.128), stage to smem,
    //          column-sum the 8 rows -> g_part. ----
    {
        const float4* xrow = X4 + ((size_t)b * N + chunk * ROWS_PER + wid) * CG;
        float4 xv[6];
#pragma unroll
        for (int k = 0; k < 6; ++k)
            xv[k] = xrow[lane + 32 * k];
#pragma unroll
        for (int k = 0; k < 6; ++k)
            xbuf[wid * CG + lane + 32 * k] = xv[k];
        __syncthreads();
        if (tid < CG) {
            float4 a0 = f4add(xbuf[tid], xbuf[CG + tid]);
            float4 a1 = f4add(xbuf[2 * CG + tid], xbuf[3 * CG + tid]);
            float4 a2 = f4add(xbuf[4 * CG + tid], xbuf[5 * CG + tid]);
            float4 a3 = f4add(xbuf[6 * CG + tid], xbuf[7 * CG + tid]);
            g_part[b][chunk][tid] = f4add(f4add(a0, a1), f4add(a2, a3));
        }
    }
    if (reducer) grid_barrier(0, ct); else grid_barrier_arrive(0);

    // ---- P2: reduce 256 partials -> s. 32 CTAs. ----
    if (reducer) {
        int bb = ct & 1, qs = ct >> 1;             // qs in [0,16)
        int base = qs * 12;
        if (tid < 192) {
            int gi = tid % 12, sl = tid / 12;      // 16 slices x 16 partials
            float4 acc = make_float4(0.f, 0.f, 0.f, 0.f);
#pragma unroll
            for (int k = 0; k < 16; ++k)
                acc = f4add(acc, g_part[bb][sl * 16 + k][base + gi]);
            sh[tid] = acc;
        }
        __syncthreads();
        if (tid < 12) {
            float4 v = make_float4(0.f, 0.f, 0.f, 0.f);
#pragma unroll
            for (int s = 0; s < 16; ++s)
                v = f4add(v, sh[s * 12 + tid]);
            ((float4*)g_s[bb])[base + tid] = v;
        }
    }
    if (p3er) grid_barrier(1, ct); else grid_barrier_arrive(1);

    // ---- P3 (ct<384): u_j = Wk_j . s; vpart = sum_j u_j * Wq_j (2 rows). ----
    if (p3er) {
        for (int i = tid; i < 2 * CG; i += T)      // stage s (both batches)
            sh[i] = (i < CG) ? ((const float4*)g_s[0])[i]
                             : ((const float4*)g_s[1])[i - CG];
        __syncthreads();
        if (wid < 2) {
            const float4* row = W4 + (size_t)(C + j0 + wid) * CG;   // Wk
            float a0 = 0.f, a1 = 0.f;
#pragma unroll
            for (int k = 0; k < 6; ++k) {
                int c4 = lane + k * 32;
                float4 w  = row[c4];
                float4 v0 = sh[c4];
                float4 v1 = sh[CG + c4];
                a0 += w.x * v0.x + w.y * v0.y + w.z * v0.z + w.w * v0.w;
                a1 += w.x * v1.x + w.y * v1.y + w.z * v1.z + w.w * v1.w;
            }
#pragma unroll
            for (int o = 16; o > 0; o >>= 1) {
                a0 += __shfl_down_sync(0xFFFFFFFFu, a0, o);
                a1 += __shfl_down_sync(0xFFFFFFFFu, a1, o);
            }
            if (lane == 0) { u0s[wid] = a0; u1s[wid] = a1; }
        }
        __syncthreads();
        if (tid < CG) {
            float4 w0 = W4[(size_t)j0 * CG + tid];         // Wq rows (L2-hot)
            float4 w1 = W4[(size_t)(j0 + 1) * CG + tid];
            float4 a0 = f4fma(w1, u0s[1], f4fma(w0, u0s[0],
                            make_float4(0.f, 0.f, 0.f, 0.f)));
            float4 a1 = f4fma(w1, u1s[1], f4fma(w0, u1s[0],
                            make_float4(0.f, 0.f, 0.f, 0.f)));
            g_vpart[0][ct][tid] = a0;
            g_vpart[1][ct][tid] = a1;
        }
    }
    if (reducer) grid_barrier(2, ct); else grid_barrier_arrive(2);

    // ---- P4: reduce 384 vparts -> v. 32 CTAs. ----
    if (reducer) {
        int bb = ct & 1, qs = ct >> 1;
        int base = qs * 12;
        if (tid < 192) {
            int gi = tid % 12, sl = tid / 12;      // 16 slices x 24 partials
            float4 acc = make_float4(0.f, 0.f, 0.f, 0.f);
#pragma unroll
            for (int k = 0; k < 24; ++k)
                acc = f4add(acc, g_vpart[bb][sl * 24 + k][base + gi]);
            sh[tid] = acc;
        }
        __syncthreads();
        if (tid < 12) {
            float4 v = make_float4(0.f, 0.f, 0.f, 0.f);
#pragma unroll
            for (int s = 0; s < 16; ++s)
                v = f4add(v, sh[s * 12 + tid]);
            ((float4*)g_v[bb])[base + tid] = v;
        }
    }
    grid_barrier(3, ct);                           // everyone needs v

    // ---- P5: warp w: scores for row chunk*8+w from retained smem X. ----
    {
        if (tid < CG) sh[tid] = ((const float4*)g_v[b])[tid];
        __syncthreads();
        float acc = 0.f;
#pragma unroll
        for (int k = 0; k < 6; ++k) {
            int c4 = lane + k * 32;
            float4 xv = xbuf[wid * CG + c4];
            float4 vv = sh[c4];
            acc += xv.x * vv.x + xv.y * vv.y + xv.z * vv.z + xv.w * vv.w;
        }
#pragma unroll
        for (int o = 16; o > 0; o >>= 1)
            acc += __shfl_down_sync(0xFFFFFFFFu, acc, o);
        if (lane == 0)
            out[b * N + chunk * ROWS_PER + wid] = 0.125f * acc;
    }
}

extern "C" void kernel_launch(void* const* d_in, const int* in_sizes, int n_in,
                              void* d_out, int out_size) {
    const float4* X4 = (const float4*)d_in[0];  // [2, 2048, 768] f32
    const float4* W4 = (const float4*)d_in[1];  // [1536, 768] f32
    float* out = (float*)d_out;                 // [2, 2048] f32
    (void)in_sizes; (void)n_in; (void)out_size;

    cudaFuncSetAttribute(fused_att_scores,
                         cudaFuncAttributeMaxDynamicSharedMemorySize, SMEM_BYTES);
    fused_att_scores<<<G, T, SMEM_BYTES>>>(X4, W4, out);
}

// round 13
// speedup vs baseline: 1.2763x; 1.2763x over previous
#include <cuda_runtime.h>
#include <cstdint>

#define B 2
#define N 2048
#define C 768
#define CG 192                     // C/4 float4 groups
#define G 256                      // 2 CTAs/SM, all co-resident
#define T 256
#define ROWS_PER 16                // X rows per CTA chunk
#define XCHUNK_BYTES (ROWS_PER * C * 4)          // 49152
#define SH_OFF XCHUNK_BYTES
#define SMEM_BYTES (XCHUNK_BYTES + 2 * CG * 16)  // 55296

__device__ float4 g_part[B][128][CG];   // P1: 128 partial colsums per batch
__device__ float  g_s[B][C];
__device__ float4 g_vpart[B][G][CG];
__device__ float  g_v[B][C];

// Each barrier counter on its own 128B line; monotonic => replay-safe.
struct __align__(128) Cnt { unsigned v; unsigned pad[31]; };
__device__ Cnt g_bar4[4];

__device__ __forceinline__ float4 f4add(float4 a, float4 b) {
    return make_float4(a.x + b.x, a.y + b.y, a.z + b.z, a.w + b.w);
}
__device__ __forceinline__ float4 f4fma(float4 a, float s, float4 acc) {
    return make_float4(fmaf(a.x, s, acc.x), fmaf(a.y, s, acc.y),
                       fmaf(a.z, s, acc.z), fmaf(a.w, s, acc.w));
}
__device__ __forceinline__ uint32_t smem_u32(const void* p) {
    uint32_t a;
    asm("{ .reg .u64 t; cvta.to.shared.u64 t, %1; cvt.u32.u64 %0, t; }"
        : "=r"(a) : "l"(p));
    return a;
}
__device__ __forceinline__ void mbar_wait(uint32_t mbar, uint32_t parity) {
    asm volatile(
        "{\n\t.reg .pred P;\n"
        "W_%=:\n\t"
        "mbarrier.try_wait.parity.shared.b64 P, [%0], %1;\n\t"
        "@!P bra W_%=;\n\t}"
        :: "r"(mbar), "r"(parity) : "memory");
}

// Fence-free grid barrier (libcudacxx grid-sync pattern): bar.sync composes
// with thread0's release-atomic to publish the whole CTA's prior writes; the
// acquire-load + bar.sync publishes the observation back to the CTA. NO
// per-thread __threadfence. Monotonic counters -> replay-safe without reset.
__device__ __forceinline__ void grid_barrier(int i) {
    __syncthreads();                    // CTA writes ordered before release
    if (threadIdx.x == 0) {
        unsigned old;
        asm volatile("atom.release.gpu.global.add.u32 %0, [%1], %2;"
                     : "=r"(old) : "l"(&g_bar4[i].v), "r"(1u) : "memory");
        unsigned target = (old / G + 1u) * G;
        unsigned cur;
        do {
            asm volatile("ld.acquire.gpu.global.u32 %0, [%1];"
                         : "=r"(cur) : "l"(&g_bar4[i].v) : "memory");
        } while (cur < target);
    }
    __syncthreads();                    // observation published to CTA
}
__device__ __forceinline__ void grid_barrier_arrive(int i) {
    __syncthreads();
    if (threadIdx.x == 0) {
        unsigned old;
        asm volatile("atom.release.gpu.global.add.u32 %0, [%1], %2;"
                     : "=r"(old) : "l"(&g_bar4[i].v), "r"(1u) : "memory");
        (void)old;
    }
}

extern __shared__ char smem_raw[];

__global__ void __launch_bounds__(T, 2)
fused_att_scores(const float4* __restrict__ X4, const float4* __restrict__ W4,
                 float* __restrict__ out) {
    float4* xbuf = (float4*)smem_raw;                 // 48 KB: this CTA's X rows
    float4* sh   = (float4*)(smem_raw + SH_OFF);      // 6 KB: s/v staging
    __shared__ uint64_t mbar_st;
    __shared__ float u0s[4], u1s[4];
    const uint32_t mbar = smem_u32(&mbar_st);
    const uint32_t xbuf_a = smem_u32(xbuf);
    const int ct  = blockIdx.x;
    const int tid = threadIdx.x;
    const bool reducer = (ct < 32);

    const int b = ct & 1, chunk = ct >> 1;            // 128 chunks per batch
    const char* xsrc = (const char*)(X4 + ((size_t)b * N + chunk * ROWS_PER) * CG);

    // ---- P1: one TMA bulk copy of 16 X rows -> smem; reduce -> g_part. ----
    if (tid == 0) {
        asm volatile("mbarrier.init.shared.b64 [%0], 1;" :: "r"(mbar) : "memory");
        asm volatile("fence.proxy.async.shared::cta;" ::: "memory");
        asm volatile(
            "mbarrier.arrive.expect_tx.shared.b64 _, [%0], %1;"
            :: "r"(mbar), "r"((uint32_t)XCHUNK_BYTES) : "memory");
        asm volatile(
            "cp.async.bulk.shared::cta.global.mbarrier::complete_tx::bytes "
            "[%0], [%1], %2, [%3];"
            :: "r"(xbuf_a), "l"(xsrc), "r"((uint32_t)XCHUNK_BYTES), "r"(mbar)
            : "memory");
    }
    __syncthreads();                 // mbar init visible to all waiters
    mbar_wait(mbar, 0);
    if (tid < CG) {
        float4 a0 = make_float4(0.f, 0.f, 0.f, 0.f), a1 = a0;
#pragma unroll
        for (int r = 0; r < ROWS_PER; r += 2) {
            a0 = f4add(a0, xbuf[r * CG + tid]);
            a1 = f4add(a1, xbuf[(r + 1) * CG + tid]);
        }
        g_part[b][chunk][tid] = f4add(a0, a1);
    }
    if (reducer) grid_barrier(0); else grid_barrier_arrive(0);

    // ---- P2: reduce 128 partials -> s. 32 CTAs. ----
    if (reducer) {
        int bb = ct & 1, qs = ct >> 1;                // qs in [0,16)
        int base = qs * 12;
        if (tid < 192) {
            int gi = tid % 12, sl = tid / 12;         // 16 slices of 8 partials
            float4 acc = make_float4(0.f, 0.f, 0.f, 0.f);
#pragma unroll
            for (int k = 0; k < 8; ++k)
                acc = f4add(acc, g_part[bb][sl * 8 + k][base + gi]);
            sh[tid] = acc;
        }
        __syncthreads();
        if (tid < 12) {
            float4 v = make_float4(0.f, 0.f, 0.f, 0.f);
#pragma unroll
            for (int s = 0; s < 16; ++s)
                v = f4add(v, sh[s * 12 + tid]);
            ((float4*)g_s[bb])[base + tid] = v;
        }
    }
    grid_barrier(1);                                  // everyone needs s

    // ---- P3 (fused rank-1): u_j = Wk_j.s; vpart += u_j * Wq_j (3 rows). ----
    {
        for (int i = tid; i < 2 * CG; i += T)         // stage s (both batches)
            sh[i] = (i < CG) ? ((const float4*)g_s[0])[i]
                             : ((const float4*)g_s[1])[i - CG];
        __syncthreads();
        int wid = tid >> 5, lane = tid & 31;
        int j0 = ct * 3;
        if (wid < 3) {
            int j = j0 + wid;
            const float4* row = W4 + (size_t)(C + j) * CG;   // Wk
            float a0 = 0.f, a1 = 0.f;
#pragma unroll
            for (int k = 0; k < 6; ++k) {
                int c4 = lane + k * 32;
                float4 w  = row[c4];
                float4 v0 = sh[c4];
                float4 v1 = sh[CG + c4];
                a0 += w.x * v0.x + w.y * v0.y + w.z * v0.z + w.w * v0.w;
                a1 += w.x * v1.x + w.y * v1.y + w.z * v1.z + w.w * v1.w;
            }
#pragma unroll
            for (int o = 16; o > 0; o >>= 1) {
                a0 += __shfl_down_sync(0xFFFFFFFFu, a0, o);
                a1 += __shfl_down_sync(0xFFFFFFFFu, a1, o);
            }
            if (lane == 0) { u0s[wid] = a0; u1s[wid] = a1; }
        }
        __syncthreads();
        if (tid < CG) {
            float4 a0 = make_float4(0.f, 0.f, 0.f, 0.f);
            float4 a1 = make_float4(0.f, 0.f, 0.f, 0.f);
#pragma unroll
            for (int jj = 0; jj < 3; ++jj) {
                float4 w = W4[(size_t)(j0 + jj) * CG + tid]; // Wq
                a0 = f4fma(w, u0s[jj], a0);
                a1 = f4fma(w, u1s[jj], a1);
            }
            g_vpart[0][ct][tid] = a0;
            g_vpart[1][ct][tid] = a1;
        }
    }
    if (reducer) grid_barrier(2); else grid_barrier_arrive(2);

    // ---- P4: reduce G partials -> v. 32 CTAs. ----
    if (reducer) {
        int bb = ct & 1, qs = ct >> 1;
        int base = qs * 12;
        if (tid < 192) {
            int gi = tid % 12, sl = tid / 12;         // 16 slices of 16 partials
            float4 acc = make_float4(0.f, 0.f, 0.f, 0.f);
#pragma unroll
            for (int k = 0; k < 16; ++k)
                acc = f4add(acc, g_vpart[bb][sl * 16 + k][base + gi]);
            sh[tid] = acc;
        }
        __syncthreads();
        if (tid < 12) {
            float4 v = make_float4(0.f, 0.f, 0.f, 0.f);
#pragma unroll
            for (int s = 0; s < 16; ++s)
                v = f4add(v, sh[s * 12 + tid]);
            ((float4*)g_v[bb])[base + tid] = v;
        }
    }
    grid_barrier(3);                                  // everyone needs v

    // ---- P5: scores from the X rows still in smem (no re-read). ----
    {
        if (tid < CG) sh[tid] = ((const float4*)g_v[b])[tid];
        __syncthreads();
        int wid = tid >> 5, lane = tid & 31;
        int nbase = chunk * ROWS_PER + wid * 2;
        float a[2];
#pragma unroll
        for (int r = 0; r < 2; ++r) {
            const float4* x = xbuf + (wid * 2 + r) * CG;
            float acc = 0.f;
#pragma unroll
            for (int k = 0; k < 6; ++k) {
                int c4 = lane + k * 32;
                float4 xv = x[c4];
                float4 vv = sh[c4];
                acc += xv.x * vv.x + xv.y * vv.y + xv.z * vv.z + xv.w * vv.w;
            }
            a[r] = acc;
        }
#pragma unroll
        for (int o = 16; o > 0; o >>= 1) {
#pragma unroll
            for (int r = 0; r < 2; ++r)
                a[r] += __shfl_down_sync(0xFFFFFFFFu, a[r], o);
        }
        if (lane == 0) {
#pragma unroll
            for (int r = 0; r < 2; ++r)
                out[b * N + nbase + r] = 0.125f * a[r];
        }
    }
}

extern "C" void kernel_launch(void* const* d_in, const int* in_sizes, int n_in,
                              void* d_out, int out_size) {
    const float4* X4 = (const float4*)d_in[0];  // [2, 2048, 768] f32
    const float4* W4 = (const float4*)d_in[1];  // [1536, 768] f32
    float* out = (float*)d_out;                 // [2, 2048] f32
    (void)in_sizes; (void)n_in; (void)out_size;

    cudaFuncSetAttribute(fused_att_scores,
                         cudaFuncAttributeMaxDynamicSharedMemorySize, SMEM_BYTES);
    fused_att_scores<<<G, T, SMEM_BYTES>>>(X4, W4, out);
}